// round 5
// baseline (speedup 1.0000x reference)
#include <cuda_runtime.h>

#define NJ    24
#define HIDD  7
#define FEATD 6
#define BATCH 500000
#define PAIRS (BATCH/2)
#define TPB   256
#define WPJ   104               // u64 pairs per joint: 13 row-chunks x 8
#define SW_N  (NJ*WPJ)          // 2496 pairs = 19968 B
#define XPAD  25
#define SX_N  (TPB*XPAD)        // 6400 pairs = 51200 B
#define SMEM_BYTES ((SW_N + SX_N) * 8)   // 71168 B

typedef unsigned long long u64;

static __device__ __forceinline__ u64 pk2(float a, float b) {
    u64 r; asm("mov.b64 %0, {%1,%2};" : "=l"(r) : "f"(a), "f"(b)); return r;
}
static __device__ __forceinline__ void upk2(u64 v, float& a, float& b) {
    asm("mov.b64 {%0,%1}, %2;" : "=f"(a), "=f"(b) : "l"(v));
}
// Packed dual FMA on the Blackwell f32x2 pipe.
static __device__ __forceinline__ u64 ffma2(u64 a, u64 b, u64 c) {
    u64 d; asm("fma.rn.f32x2 %0, %1, %2, %3;" : "=l"(d) : "l"(a), "l"(b), "l"(c)); return d;
}
static __device__ __forceinline__ u64 relu2(u64 v) {
    float a, b; upk2(v, a, b);
    return pk2(fmaxf(a, 0.f), fmaxf(b, 0.f));
}

__global__ __launch_bounds__(TPB, 3)
void se1d_kernel(const float* __restrict__ x,
                 const float* __restrict__ W1, const float* __restrict__ b1,
                 const float* __restrict__ W2, const float* __restrict__ b2,
                 float* __restrict__ out)
{
    extern __shared__ u64 smem[];
    u64* sw = smem;             // [SW_N] weights, duplicated {w,w} pairs
    u64* sx = smem + SW_N;      // [SX_N] per-thread x pairs, pad 25

    // Weight layout per joint j (13 row-chunks of 8 pairs, each 64B-aligned):
    //   rows 0..6 :  {b1[r],   W1[r][0..6]}
    //   rows 7..12:  {b2[r-7], W2[r-7][0..6]}
    for (int idx = threadIdx.x; idx < SW_N; idx += TPB) {
        int j = idx / WPJ, o = idx % WPJ;
        int row = o >> 3, s = o & 7;
        float v;
        if (row < 7) v = (s == 0) ? b1[j*7 + row]     : W1[j*49 + row*7     + (s-1)];
        else         v = (s == 0) ? b2[j*6 + (row-7)] : W2[j*42 + (row-7)*7 + (s-1)];
        sw[idx] = pk2(v, v);
    }
    __syncthreads();

    const int pair = blockIdx.x * TPB + threadIdx.x;
    if (pair >= PAIRS) return;

    // Stage this thread's two x rows into smem (own data only -> no sync).
    // Coalesced: warp covers 6144B contiguous via LDG.128.
    {
        const float4* xr = (const float4*)(x + (long)pair * 48);
        u64* my = sx + threadIdx.x * XPAD;
        #pragma unroll
        for (int q = 0; q < 6; q++) {
            float4 a = xr[q];       // row 2t
            float4 b = xr[q + 6];   // row 2t+1
            my[q*4+0] = pk2(a.x, b.x);
            my[q*4+1] = pk2(a.y, b.y);
            my[q*4+2] = pk2(a.z, b.z);
            my[q*4+3] = pk2(a.w, b.w);
        }
    }

    float* o0 = out + (long)pair * 288;
    float* o1 = o0 + 144;
    const u64* my = sx + threadIdx.x * XPAD;

    // DFS order: max live feature set = 2 joints (12 pairs = 24 regs).
    const int ORDER[NJ] = {0,1,4,7,10, 2,5,8,11, 3,6,9, 12,15, 13,16,18,20,22, 14,17,19,21,23};
    const int PAR[NJ]   = {-1,0,0,0,1,2,3,4,5,6,7,8,9,9,9,12,13,14,16,17,18,19,20,21};

    u64 feat[NJ][FEATD];   // SROA'd; dead entries eliminated by liveness

    #pragma unroll
    for (int k = 0; k < NJ; k++) {
        const int j = ORDER[k];
        const int p = PAR[j];
        const u64* wj = sw + j * WPJ;

        u64 inp[HIDD];
        inp[0] = my[j];                       // LDS.64, conflict-free
        #pragma unroll
        for (int c = 0; c < FEATD; c++)
            inp[c+1] = (p >= 0) ? feat[p][c] : 0ull;

        // Layer 1: 7x7, weights fetched as 4x LDS.128 per row
        u64 h[HIDD];
        #pragma unroll
        for (int r = 0; r < HIDD; r++) {
            const ulonglong2* rw = (const ulonglong2*)(wj + r*8);
            ulonglong2 q0 = rw[0], q1 = rw[1], q2 = rw[2], q3 = rw[3];
            u64 acc = q0.x;                   // bias pair
            acc = ffma2(q0.y, inp[0], acc);
            acc = ffma2(q1.x, inp[1], acc);
            acc = ffma2(q1.y, inp[2], acc);
            acc = ffma2(q2.x, inp[3], acc);
            acc = ffma2(q2.y, inp[4], acc);
            acc = ffma2(q3.x, inp[5], acc);
            acc = ffma2(q3.y, inp[6], acc);
            h[r] = relu2(acc);
        }

        // Layer 2: 6x7
        u64 f[FEATD];
        #pragma unroll
        for (int r = 0; r < FEATD; r++) {
            const ulonglong2* rw = (const ulonglong2*)(wj + (7 + r)*8);
            ulonglong2 q0 = rw[0], q1 = rw[1], q2 = rw[2], q3 = rw[3];
            u64 acc = q0.x;                   // bias pair
            acc = ffma2(q0.y, h[0], acc);
            acc = ffma2(q1.x, h[1], acc);
            acc = ffma2(q1.y, h[2], acc);
            acc = ffma2(q2.x, h[3], acc);
            acc = ffma2(q2.y, h[4], acc);
            acc = ffma2(q3.x, h[5], acc);
            acc = ffma2(q3.y, h[6], acc);
            f[r] = relu2(acc);
        }

        // Direct stores: 3x STG.64 per row (8B-aligned since j*24B % 8 == 0)
        float lo[FEATD], hi[FEATD];
        #pragma unroll
        for (int r = 0; r < FEATD; r++) upk2(f[r], lo[r], hi[r]);
        *(float2*)(o0 + j*6 + 0) = make_float2(lo[0], lo[1]);
        *(float2*)(o0 + j*6 + 2) = make_float2(lo[2], lo[3]);
        *(float2*)(o0 + j*6 + 4) = make_float2(lo[4], lo[5]);
        *(float2*)(o1 + j*6 + 0) = make_float2(hi[0], hi[1]);
        *(float2*)(o1 + j*6 + 2) = make_float2(hi[2], hi[3]);
        *(float2*)(o1 + j*6 + 4) = make_float2(hi[4], hi[5]);

        #pragma unroll
        for (int r = 0; r < FEATD; r++) feat[j][r] = f[r];
    }
}

extern "C" void kernel_launch(void* const* d_in, const int* in_sizes, int n_in,
                              void* d_out, int out_size)
{
    const float* x  = (const float*)d_in[0];
    const float* W1 = (const float*)d_in[1];
    const float* b1 = (const float*)d_in[2];
    const float* W2 = (const float*)d_in[3];
    const float* b2 = (const float*)d_in[4];
    float* out = (float*)d_out;

    cudaFuncSetAttribute(se1d_kernel,
                         cudaFuncAttributeMaxDynamicSharedMemorySize, SMEM_BYTES);

    const int blocks = (PAIRS + TPB - 1) / TPB;
    se1d_kernel<<<blocks, TPB, SMEM_BYTES>>>(x, W1, b1, W2, b2, out);
}

// round 6
// speedup vs baseline: 2.5124x; 2.5124x over previous
#include <cuda_runtime.h>

#define NJ    24
#define BATCH 500000
#define PAIRS (BATCH/2)
#define TPB   256
#define WPJ   104              // u64 pairs per joint: 7 b1 + 49 W1 + 6 b2 + 42 W2
#define SW_N  (NJ*WPJ)         // 2496 pairs = 19968 B static smem

typedef unsigned long long u64;

static __device__ __forceinline__ u64 pk2(float a, float b) {
    u64 r; asm("mov.b64 %0, {%1,%2};" : "=l"(r) : "f"(a), "f"(b)); return r;
}
static __device__ __forceinline__ void upk2(u64 v, float& a, float& b) {
    asm("mov.b64 {%0,%1}, %2;" : "=f"(a), "=f"(b) : "l"(v));
}
// Packed dual FMA on the Blackwell f32x2 pipe.
static __device__ __forceinline__ u64 ffma2(u64 a, u64 b, u64 c) {
    u64 d; asm("fma.rn.f32x2 %0, %1, %2, %3;" : "=l"(d) : "l"(a), "l"(b), "l"(c)); return d;
}
static __device__ __forceinline__ u64 relu2(u64 v) {
    float a, b; upk2(v, a, b);
    return pk2(fmaxf(a, 0.f), fmaxf(b, 0.f));
}

__global__ __launch_bounds__(TPB, 2)
void se1d_kernel(const float* __restrict__ x,
                 const float* __restrict__ W1, const float* __restrict__ b1,
                 const float* __restrict__ W2, const float* __restrict__ b2,
                 float* __restrict__ out)
{
    // Weights in static shared, duplicated {w,w} pairs, exact consumption order
    // (round-1 proven layout): per joint: 7 b1 | 49 W1 row-major | 6 b2 | 42 W2 row-major
    __shared__ u64 sw[SW_N];
    for (int idx = threadIdx.x; idx < SW_N; idx += TPB) {
        int j = idx / WPJ, o = idx - j * WPJ;
        float v;
        if (o < 7)        v = b1[j*7 + o];
        else if (o < 56)  v = W1[j*49 + (o-7)];
        else if (o < 62)  v = b2[j*6 + (o-56)];
        else              v = W2[j*42 + (o-62)];
        sw[idx] = pk2(v, v);
    }
    __syncthreads();

    const int pair = blockIdx.x * TPB + threadIdx.x;
    if (pair >= PAIRS) return;

    const float4* xr0 = (const float4*)(x + (long)pair * 48);  // row 2t
    const float4* xr1 = xr0 + 6;                               // row 2t+1
    float* o0 = out + (long)pair * 288;
    float* o1 = o0 + 144;

    u64 xp[4];             // JIT x chunk: 4 joints at a time
    u64 feat[NJ][6];       // literal indices only -> SROA'd, max ~3 joints live
    float s0[12], s1[12];  // 2-joint output staging

// Load x chunk q: covers joints 4q..4q+3 (pure register rotation, all literal).
#define LOADX(q) do { \
    float4 a_ = xr0[q], b_ = xr1[q]; \
    xp[0] = pk2(a_.x, b_.x); xp[1] = pk2(a_.y, b_.y); \
    xp[2] = pk2(a_.z, b_.z); xp[3] = pk2(a_.w, b_.w); \
} while (0)

// Layer-1 row r for joint j with parent p (HAS_P is a literal 0/1 -> dead-code folds).
#define L1ROW(dst, p, HAS_P, r) do { \
    u64 acc_ = wj_[(r)]; \
    acc_ = ffma2(wj_[7+(r)*7+0], in0_, acc_); \
    if (HAS_P) { \
        acc_ = ffma2(wj_[7+(r)*7+1], feat[p][0], acc_); \
        acc_ = ffma2(wj_[7+(r)*7+2], feat[p][1], acc_); \
        acc_ = ffma2(wj_[7+(r)*7+3], feat[p][2], acc_); \
        acc_ = ffma2(wj_[7+(r)*7+4], feat[p][3], acc_); \
        acc_ = ffma2(wj_[7+(r)*7+5], feat[p][4], acc_); \
        acc_ = ffma2(wj_[7+(r)*7+6], feat[p][5], acc_); \
    } \
    dst = relu2(acc_); \
} while (0)

// Layer-2 row r for joint j: writes feat + staging (all indices literal).
#define L2ROW(j, r) do { \
    u64 acc_ = wj_[56 + (r)]; \
    acc_ = ffma2(wj_[62+(r)*7+0], h0_, acc_); \
    acc_ = ffma2(wj_[62+(r)*7+1], h1_, acc_); \
    acc_ = ffma2(wj_[62+(r)*7+2], h2_, acc_); \
    acc_ = ffma2(wj_[62+(r)*7+3], h3_, acc_); \
    acc_ = ffma2(wj_[62+(r)*7+4], h4_, acc_); \
    acc_ = ffma2(wj_[62+(r)*7+5], h5_, acc_); \
    acc_ = ffma2(wj_[62+(r)*7+6], h6_, acc_); \
    u64 fv_ = relu2(acc_); \
    feat[j][r] = fv_; \
    float lo_, hi_; upk2(fv_, lo_, hi_); \
    s0[((j)&1)*6 + (r)] = lo_; \
    s1[((j)&1)*6 + (r)] = hi_; \
} while (0)

#define JOINT(j, HAS_P, p) do { \
    const u64* wj_ = sw + (j)*WPJ; \
    const u64 in0_ = xp[(j)&3]; \
    u64 h0_, h1_, h2_, h3_, h4_, h5_, h6_; \
    L1ROW(h0_, p, HAS_P, 0); L1ROW(h1_, p, HAS_P, 1); \
    L1ROW(h2_, p, HAS_P, 2); L1ROW(h3_, p, HAS_P, 3); \
    L1ROW(h4_, p, HAS_P, 4); L1ROW(h5_, p, HAS_P, 5); \
    L1ROW(h6_, p, HAS_P, 6); \
    L2ROW(j, 0); L2ROW(j, 1); L2ROW(j, 2); \
    L2ROW(j, 3); L2ROW(j, 4); L2ROW(j, 5); \
} while (0)

// Flush 2 joints (j-1, j) per output row as 3 aligned STG.128 each.
#define FLUSH(j) do { \
    const int base_ = ((j)-1)*6; \
    *(float4*)(o0+base_+0) = make_float4(s0[0], s0[1], s0[2],  s0[3]); \
    *(float4*)(o0+base_+4) = make_float4(s0[4], s0[5], s0[6],  s0[7]); \
    *(float4*)(o0+base_+8) = make_float4(s0[8], s0[9], s0[10], s0[11]); \
    *(float4*)(o1+base_+0) = make_float4(s1[0], s1[1], s1[2],  s1[3]); \
    *(float4*)(o1+base_+4) = make_float4(s1[4], s1[5], s1[6],  s1[7]); \
    *(float4*)(o1+base_+8) = make_float4(s1[8], s1[9], s1[10], s1[11]); \
} while (0)

    // Topological order 0..23 (PARENTS[i] < i), parents as literals.
    LOADX(0);
    JOINT(0, 0, 0);   JOINT(1, 1, 0);   FLUSH(1);
    JOINT(2, 1, 0);   JOINT(3, 1, 0);   FLUSH(3);
    LOADX(1);
    JOINT(4, 1, 1);   JOINT(5, 1, 2);   FLUSH(5);
    JOINT(6, 1, 3);   JOINT(7, 1, 4);   FLUSH(7);
    LOADX(2);
    JOINT(8, 1, 5);   JOINT(9, 1, 6);   FLUSH(9);
    JOINT(10, 1, 7);  JOINT(11, 1, 8);  FLUSH(11);
    LOADX(3);
    JOINT(12, 1, 9);  JOINT(13, 1, 9);  FLUSH(13);
    JOINT(14, 1, 9);  JOINT(15, 1, 12); FLUSH(15);
    LOADX(4);
    JOINT(16, 1, 13); JOINT(17, 1, 14); FLUSH(17);
    JOINT(18, 1, 16); JOINT(19, 1, 17); FLUSH(19);
    LOADX(5);
    JOINT(20, 1, 18); JOINT(21, 1, 19); FLUSH(21);
    JOINT(22, 1, 20); JOINT(23, 1, 21); FLUSH(23);
}

extern "C" void kernel_launch(void* const* d_in, const int* in_sizes, int n_in,
                              void* d_out, int out_size)
{
    const float* x  = (const float*)d_in[0];
    const float* W1 = (const float*)d_in[1];
    const float* b1 = (const float*)d_in[2];
    const float* W2 = (const float*)d_in[3];
    const float* b2 = (const float*)d_in[4];
    float* out = (float*)d_out;

    const int blocks = (PAIRS + TPB - 1) / TPB;
    se1d_kernel<<<blocks, TPB>>>(x, W1, b1, W2, b2, out);
}